// round 12
// baseline (speedup 1.0000x reference)
#include <cuda_runtime.h>
#include <math.h>

typedef unsigned long long ull;

// Problem constants
#define DHID   1024
#define BATCH  32
#define TSTEPS 513           // GRU steps (U+1)
#define N3     3072
#define NCTA   128           // persistent grid: 8 hidden units per CTA, 1 CTA/SM
#define NGRP   16            // producer groups (8 CTAs each) = consumer k-slices

// SMEM: Wh row-pair-packed [1024 k][16 ull] (128KB) + exchange [16 w][24 r][33] (49.5KB)
#define SWH_ULLS   (1024 * 16)
#define SEX_FLOATS (16 * 24 * 33)
#define STEP_SMEM  (SWH_ULLS * 8 + SEX_FLOATS * 4)   // 181760 bytes

// ---------------- f32x2 packed helpers ----------------
#define FMA2(acc, a, b) asm("fma.rn.f32x2 %0, %1, %2, %0;" : "+l"(acc) : "l"(a), "l"(b))
#define PACKDUP(d, v)   asm("mov.b64 %0, {%1, %1};" : "=l"(d) : "f"(v))
#define PACK2(d, lo, hi) asm("mov.b64 %0, {%1, %2};" : "=l"(d) : "f"(lo), "f"(hi))
#define UNPK(lo, hi, v) asm("mov.b64 {%0, %1}, %2;" : "=f"(lo), "=f"(hi) : "l"(v))

// ---------------- device scratch (no allocation allowed) ----------------
__device__ float g_Eproj[1024 * N3];                       // embed @ Wx + bx (12.6 MB)
__device__ uint4 g_WhT4[(size_t)N3 * (DHID / 4)];          // Wh^T [3D][D]
__device__ float g_hb[(size_t)(TSTEPS + 1) * DHID * BATCH]; // h [s][k(=unit j)][b] (67.4 MB)
__device__ unsigned g_scnt[(TSTEPS + 1) * NGRP];           // per-step per-group counters

// ---------------- init: h0 broadcast into g_hb[0] + counter reset ----------------
__global__ void init_kernel(const float* __restrict__ h0) {
    int idx = blockIdx.x * blockDim.x + threadIdx.x;       // 32768 threads
    g_hb[idx] = h0[idx >> 5];                              // [k][b], b = idx&31
    if (idx < (TSTEPS + 1) * NGRP) g_scnt[idx] = 0;
}

// ---------------- transpose Wh [D,3D] -> WhT [3D,D] ----------------
__global__ void transpose_wh_kernel(const float* __restrict__ Wh) {
    __shared__ float t[32][33];
    int j = blockIdx.x * 32 + threadIdx.x;
    int d = blockIdx.y * 32 + threadIdx.y;
    t[threadIdx.y][threadIdx.x] = Wh[(size_t)d * N3 + j];
    __syncthreads();
    int dd = blockIdx.y * 32 + threadIdx.x;
    int jj = blockIdx.x * 32 + threadIdx.y;
    ((float*)g_WhT4)[(size_t)jj * DHID + dd] = t[threadIdx.x][threadIdx.y];
}

// ---------------- packed-fp32 tiled GEMM: C = A*B + bias ----------------
// mode 0: A row-major [M,K], C[row*N+col]
// mode 1: A = h in [t][j][b] layout (A base = g_hb + 32768): row gr=(t<<5)|b,
//         element A[gr][j] = Abase[(t*1024 + j)*32 + b]; C[(b*513+t)*1024+col]
__global__ __launch_bounds__(256)
void gemm_bias_kernel(const float* __restrict__ A, const float* __restrict__ Bm,
                      const float* __restrict__ bias, float* __restrict__ C,
                      int M, int N, int K, int mode) {
    __shared__ ull   sAd[32][65];
    __shared__ float sB[32][64];
    int bm = blockIdx.y * 64, bn = blockIdx.x * 64;
    int tid = threadIdx.x;
    int tr = tid >> 4, tc = tid & 15;
    ull acc[4][2];
#pragma unroll
    for (int i = 0; i < 4; i++) { acc[i][0] = 0ull; acc[i][1] = 0ull; }

    for (int k0 = 0; k0 < K; k0 += 32) {
        if (mode == 0) {
#pragma unroll
            for (int i = tid; i < 64 * 32; i += 256) {
                int r = i >> 5, cc = i & 31;
                int gr = bm + r;
                float v = (gr < M) ? A[(size_t)gr * K + k0 + cc] : 0.f;
                ull dv; PACKDUP(dv, v);
                sAd[cc][r] = dv;
            }
        } else {
            // transposing load from g_hb: coalesced along b
#pragma unroll
            for (int i = tid; i < 64 * 32; i += 256) {
                int cc = i >> 6, r = i & 63;
                int gr = bm + r;
                float v = 0.f;
                if (gr < M) {
                    int t = gr >> 5, b = gr & 31;
                    v = A[((size_t)t * 1024 + k0 + cc) * 32 + b];
                }
                ull dv; PACKDUP(dv, v);
                sAd[cc][r] = dv;
            }
        }
#pragma unroll
        for (int i = tid; i < 32 * 64; i += 256) {
            int r = i >> 6, cc = i & 63;
            sB[r][cc] = Bm[(size_t)(k0 + r) * N + bn + cc];
        }
        __syncthreads();
#pragma unroll
        for (int kk = 0; kk < 32; kk++) {
            ull a0 = sAd[kk][tr * 4 + 0];
            ull a1 = sAd[kk][tr * 4 + 1];
            ull a2 = sAd[kk][tr * 4 + 2];
            ull a3 = sAd[kk][tr * 4 + 3];
            ull b0 = *(const ull*)&sB[kk][tc * 4];
            ull b1 = *(const ull*)&sB[kk][tc * 4 + 2];
            FMA2(acc[0][0], a0, b0); FMA2(acc[0][1], a0, b1);
            FMA2(acc[1][0], a1, b0); FMA2(acc[1][1], a1, b1);
            FMA2(acc[2][0], a2, b0); FMA2(acc[2][1], a2, b1);
            FMA2(acc[3][0], a3, b0); FMA2(acc[3][1], a3, b1);
        }
        __syncthreads();
    }
#pragma unroll
    for (int i = 0; i < 4; i++) {
        int row = bm + tr * 4 + i;
        if (row >= M) continue;
#pragma unroll
        for (int j2 = 0; j2 < 2; j2++) {
            float lo, hi; UNPK(lo, hi, acc[i][j2]);
            int c0 = bn + tc * 4 + 2 * j2;
            float v0 = lo + bias[c0];
            float v1 = hi + bias[c0 + 1];
            if (mode == 0) {
                C[(size_t)row * N + c0]     = v0;
                C[(size_t)row * N + c0 + 1] = v1;
            } else {
                int t = row >> 5, b = row & 31;
                size_t o = ((size_t)b * 513 + t) * 1024 + c0;
                C[o]     = v0;
                C[o + 1] = v1;
            }
        }
    }
}

// ---------------- persistent GRU recurrence (group dataflow sync) ----------------
// 128 CTAs x 512 threads. CTA owns 24 rows (units jbase..jbase+7), row-pair-
// packed Wh in SMEM. Lane = (bg = lane>>2: 4 batches, rg = lane&3: 3 row-pairs).
// Warp w: k-slice [w*64, w*64+64) = h-units produced by CTA group [8w, 8w+8).
// Sync is DATAFLOW, not a global barrier: each CTA red.release's ONE group
// counter g_scnt[s][bid>>3] after its epilogue; consumer warp w acquire-polls
// (lane 0 only) g_scnt[s-1][w] == 8 before touching h[s-1] slice w. No global
// convergence point -> straggler CTAs delay only their dependent slices.
__global__ __launch_bounds__(512, 1)
void gru_persist_kernel(const float* __restrict__ bh, const int* __restrict__ y) {
    extern __shared__ ull smu[];
    ull*   swh = smu;                          // [1024][16] ull
    float* sex = (float*)(smu + SWH_ULLS);     // [16][24][33]

    const int tid  = threadIdx.x;
    const int lane = tid & 31;
    const int w    = tid >> 5;                 // 0..15
    const int bg   = lane >> 2;                // 0..7 (4 batches each)
    const int rg   = lane & 3;                 // 0..3 (3 row-pairs each)
    const int jbase = blockIdx.x * 8;

    // one-time: build row-pair-packed Wh in SMEM.
    // pair a (0..11) covers rows ru=2a,2a+1; ru=(u*3+g) -> WhT row g*1024+jbase+u
    const float* WhTf = (const float*)g_WhT4;
    for (int idx = tid; idx < 12 * 1024; idx += 512) {
        int a = idx >> 10, k = idx & 1023;
        int ru0 = 2 * a, ru1 = 2 * a + 1;
        int r0 = (ru0 % 3) * 1024 + jbase + ru0 / 3;
        int r1 = (ru1 % 3) * 1024 + jbase + ru1 / 3;
        float w0 = WhTf[(size_t)r0 * 1024 + k];
        float w1 = WhTf[(size_t)r1 * 1024 + k];
        ull pk; PACK2(pk, w0, w1);
        swh[(size_t)k * 16 + (a / 3) * 4 + (a % 3)] = pk;
    }

    // epilogue constants: thread (u = w, b = lane) for tid < 256
    const bool epi = (tid < 256);
    const int ju = epi ? (jbase + w) : jbase;
    float bz = 0.f, br = 0.f, bq = 0.f, hold = 0.f;
    if (epi) {
        bz = bh[ju]; br = bh[DHID + ju]; bq = bh[2 * DHID + ju];
        hold = ((const float*)g_hb)[(size_t)ju * 32 + lane];   // = h0[ju]
    }
    __syncthreads();

    const int k0w = w * 64;
    const ull* swk = swh + (size_t)k0w * 16 + rg * 4;

    for (int s = 1; s <= TSTEPS; ++s) {
        // prefetch epilogue inputs (independent of h[s-1])
        float ez = 0.f, er = 0.f, eq = 0.f;
        if (epi) {
            int tok = (s == 1) ? 0 : __ldg(&y[lane * 512 + (s - 2)]);
            const float* ep = g_Eproj + (size_t)tok * N3;
            ez = __ldg(ep + ju);
            er = __ldg(ep + DHID + ju);
            eq = __ldg(ep + 2 * DHID + ju);
        }

        // ---- dataflow wait: slice w of h[s-1] ready when its 8 producer CTAs
        //      have released (lane 0 polls, others wait at syncwarp) ----
        if (s >= 2) {
            if (lane == 0) {
                const unsigned* cp = &g_scnt[(s - 1) * NGRP + w];
                unsigned v;
                do {
                    asm volatile("ld.acquire.gpu.global.u32 %0, [%1];"
                                 : "=r"(v) : "l"(cp) : "memory");
                } while (v < 8u);
            }
            __syncwarp();
        }

        // ---- main reduction: 64 k, 12 row-pairs x 4 batches per lane ----
        ull acc[12];
#pragma unroll
        for (int r = 0; r < 12; r++) acc[r] = 0ull;

        const float* hbase = g_hb + ((size_t)(s - 1) * 1024 + k0w) * 32 + bg * 4;

        // depth-8 prefetch pipeline (MLP=8)
        uint4 hpre[8];
#pragma unroll
        for (int i = 0; i < 8; i++)
            hpre[i] = __ldcg((const uint4*)(hbase + (size_t)i * 32));

#pragma unroll 8
        for (int kk = 0; kk < 64; kk++) {
            uint4 hc = hpre[kk & 7];
            int pf = (kk + 8 <= 63) ? (kk + 8) : 63;     // clamp inside slice
            hpre[kk & 7] = __ldcg((const uint4*)(hbase + (size_t)pf * 32));

            const ull* wk = swk + (size_t)kk * 16;
            ulonglong2 wv01 = *(const ulonglong2*)wk;
            ull wv2 = wk[2];

            ull hd0, hd1, hd2, hd3;
            PACKDUP(hd0, __uint_as_float(hc.x));
            PACKDUP(hd1, __uint_as_float(hc.y));
            PACKDUP(hd2, __uint_as_float(hc.z));
            PACKDUP(hd3, __uint_as_float(hc.w));

            FMA2(acc[0], wv01.x, hd0); FMA2(acc[1], wv01.x, hd1);
            FMA2(acc[2], wv01.x, hd2); FMA2(acc[3], wv01.x, hd3);
            FMA2(acc[4], wv01.y, hd0); FMA2(acc[5], wv01.y, hd1);
            FMA2(acc[6], wv01.y, hd2); FMA2(acc[7], wv01.y, hd3);
            FMA2(acc[8],  wv2,   hd0); FMA2(acc[9],  wv2,   hd1);
            FMA2(acc[10], wv2,   hd2); FMA2(acc[11], wv2,   hd3);
        }

        // exchange: unpack row-pairs, store floats sex[w][ru][b]
#pragma unroll
        for (int p = 0; p < 3; p++) {
#pragma unroll
            for (int bb = 0; bb < 4; bb++) {
                float lo, hi; UNPK(lo, hi, acc[p * 4 + bb]);
                int ru = (rg * 3 + p) * 2;
                int b  = bg * 4 + bb;
                sex[(w * 24 + ru)     * 33 + b] = lo;
                sex[(w * 24 + ru + 1) * 33 + b] = hi;
            }
        }
        __syncthreads();

        // ---- epilogue: thread (u=w, b=lane), tid < 256 ----
        if (epi) {
            float hz = bz, hr = br, hqv = bq;
#pragma unroll
            for (int w2 = 0; w2 < 16; w2++) {
                int base = (w2 * 24 + w * 3) * 33 + lane;
                hz  += sex[base];
                hr  += sex[base + 33];
                hqv += sex[base + 66];
            }
            float zg = __fdividef(1.f, 1.f + __expf(-(ez + hz)));
            float rg2 = __fdividef(1.f, 1.f + __expf(-(er + hr)));
            float xq = eq + rg2 * hqv;
            float e2 = __expf(2.f * xq);
            float hc = 1.f - __fdividef(2.f, e2 + 1.f);
            float hn = zg * hold + (1.f - zg) * hc;
            hold = hn;

            __stcg(&g_hb[((size_t)s * 1024 + ju) * 32 + lane], hn);
        }

        // protect sex from next step's publish until epilogue has read it
        __syncthreads();

        // ---- publish: this CTA's slice of h[s] is ready (group bid>>3) ----
        if (s < TSTEPS && tid == 0) {
            asm volatile("red.release.gpu.global.add.u32 [%0], %1;"
                         :: "l"(&g_scnt[s * NGRP + (blockIdx.x >> 3)]), "r"(1u)
                         : "memory");
        }
    }
}

// ---------------- launch ----------------
extern "C" void kernel_launch(void* const* d_in, const int* in_sizes, int n_in,
                              void* d_out, int out_size) {
    const int*   y   = (const int*)d_in[0];
    const float* emb = (const float*)d_in[1];
    const float* Wx  = (const float*)d_in[2];
    const float* Wh  = (const float*)d_in[3];
    const float* bx  = (const float*)d_in[4];
    const float* bh  = (const float*)d_in[5];
    const float* Wd  = (const float*)d_in[6];
    const float* bd  = (const float*)d_in[7];
    const float* h0  = (const float*)d_in[8];
    float* out = (float*)d_out;

    float *pE, *pHb;
    cudaGetSymbolAddress((void**)&pE, g_Eproj);
    cudaGetSymbolAddress((void**)&pHb, g_hb);

    cudaFuncSetAttribute(gru_persist_kernel,
                         cudaFuncAttributeMaxDynamicSharedMemorySize, STEP_SMEM);

    // init h0 into g_hb[0] + reset dataflow counters (every replay)
    init_kernel<<<32, 1024>>>(h0);
    // WhT = transpose(Wh)
    transpose_wh_kernel<<<dim3(96, 32), dim3(32, 32)>>>(Wh);
    // Eproj = embed_table @ Wx + bx (only 1024 distinct token rows)
    gemm_bias_kernel<<<dim3(48, 16), 256>>>(emb, Wx, bx, pE, 1024, N3, 1024, 0);
    // persistent GRU recurrence (513 steps, one launch, group-dataflow sync)
    gru_persist_kernel<<<NCTA, 512, STEP_SMEM>>>(bh, y);
    // outs[b,t,:] = h_{t+1}[b,:] @ Wd + bd  (A read transposed from g_hb, s>=1)
    gemm_bias_kernel<<<dim3(16, 257), 256>>>(pHb + 32768, Wd, bd, out,
                                             TSTEPS * BATCH, 1024, 1024, 1);
}

// round 13
// speedup vs baseline: 1.0422x; 1.0422x over previous
#include <cuda_runtime.h>
#include <math.h>

typedef unsigned long long ull;

#define DHID   1024
#define BATCH  32
#define TSTEPS 513
#define N3     3072
#define NCTA   128

// SMEM layout (bytes): swh 131072 | sex 50688 | sWd 32768 | pg 16384 = 230912
#define SWH_ULLS   (1024 * 16)
#define SEX_FLOATS (16 * 24 * 33)
#define SWD_OFF_B  (SWH_ULLS * 8 + SEX_FLOATS * 4)
#define PG_OFF_B   (SWD_OFF_B + 1024 * 4 * 8)
#define STEP_SMEM  (PG_OFF_B + 16 * 32 * 4 * 8)

#define FMA2(acc, a, b) asm("fma.rn.f32x2 %0, %1, %2, %0;" : "+l"(acc) : "l"(a), "l"(b))
#define ADD2(acc, a)    asm("add.rn.f32x2 %0, %0, %1;" : "+l"(acc) : "l"(a))
#define PACKDUP(d, v)   asm("mov.b64 %0, {%1, %1};" : "=l"(d) : "f"(v))
#define PACK2(d, lo, hi) asm("mov.b64 %0, {%1, %2};" : "=l"(d) : "f"(lo), "f"(hi))
#define UNPK(lo, hi, v) asm("mov.b64 {%0, %1}, %2;" : "=f"(lo), "=f"(hi) : "l"(v))

__device__ float g_Eproj[1024 * N3];
__device__ uint4 g_WhT4[(size_t)N3 * (DHID / 4)];
__device__ float g_hb[(size_t)(TSTEPS + 1) * DHID * BATCH];
__device__ ull   g_Wdp[(size_t)1024 * 512];      // Wd packed col-pairs [k][512]
__device__ unsigned g_cnt[TSTEPS + 2];

__global__ void init_kernel(const float* __restrict__ h0) {
    int idx = blockIdx.x * blockDim.x + threadIdx.x;
    g_hb[idx] = h0[idx >> 5];
    if (idx < TSTEPS + 2) g_cnt[idx] = 0;
}

__global__ void transpose_wh_kernel(const float* __restrict__ Wh) {
    __shared__ float t[32][33];
    int j = blockIdx.x * 32 + threadIdx.x;
    int d = blockIdx.y * 32 + threadIdx.y;
    t[threadIdx.y][threadIdx.x] = Wh[(size_t)d * N3 + j];
    __syncthreads();
    int dd = blockIdx.y * 32 + threadIdx.x;
    int jj = blockIdx.x * 32 + threadIdx.y;
    ((float*)g_WhT4)[(size_t)jj * DHID + dd] = t[threadIdx.x][threadIdx.y];
}

__global__ void pack_wd_kernel(const float* __restrict__ Wd) {
    int idx = blockIdx.x * blockDim.x + threadIdx.x;     // 1024*512
    int k = idx >> 9, p = idx & 511;
    ull v; PACK2(v, Wd[(size_t)k * 1024 + 2 * p], Wd[(size_t)k * 1024 + 2 * p + 1]);
    g_Wdp[idx] = v;
}

// Eproj GEMM: C = A[M,K]*B[K,N] + bias (row-major)
__global__ __launch_bounds__(256)
void gemm_bias_kernel(const float* __restrict__ A, const float* __restrict__ Bm,
                      const float* __restrict__ bias, float* __restrict__ C,
                      int M, int N, int K) {
    __shared__ ull   sAd[32][65];
    __shared__ float sB[32][64];
    int bm = blockIdx.y * 64, bn = blockIdx.x * 64;
    int tid = threadIdx.x;
    int tr = tid >> 4, tc = tid & 15;
    ull acc[4][2];
#pragma unroll
    for (int i = 0; i < 4; i++) { acc[i][0] = 0ull; acc[i][1] = 0ull; }
    for (int k0 = 0; k0 < K; k0 += 32) {
#pragma unroll
        for (int i = tid; i < 64 * 32; i += 256) {
            int r = i >> 5, cc = i & 31;
            int gr = bm + r;
            float v = (gr < M) ? A[(size_t)gr * K + k0 + cc] : 0.f;
            ull dv; PACKDUP(dv, v);
            sAd[cc][r] = dv;
        }
#pragma unroll
        for (int i = tid; i < 32 * 64; i += 256) {
            int r = i >> 6, cc = i & 63;
            sB[r][cc] = Bm[(size_t)(k0 + r) * N + bn + cc];
        }
        __syncthreads();
#pragma unroll
        for (int kk = 0; kk < 32; kk++) {
            ull a0 = sAd[kk][tr * 4 + 0];
            ull a1 = sAd[kk][tr * 4 + 1];
            ull a2 = sAd[kk][tr * 4 + 2];
            ull a3 = sAd[kk][tr * 4 + 3];
            ull b0 = *(const ull*)&sB[kk][tc * 4];
            ull b1 = *(const ull*)&sB[kk][tc * 4 + 2];
            FMA2(acc[0][0], a0, b0); FMA2(acc[0][1], a0, b1);
            FMA2(acc[1][0], a1, b0); FMA2(acc[1][1], a1, b1);
            FMA2(acc[2][0], a2, b0); FMA2(acc[2][1], a2, b1);
            FMA2(acc[3][0], a3, b0); FMA2(acc[3][1], a3, b1);
        }
        __syncthreads();
    }
#pragma unroll
    for (int i = 0; i < 4; i++) {
        int row = bm + tr * 4 + i;
        if (row >= M) continue;
#pragma unroll
        for (int j2 = 0; j2 < 2; j2++) {
            float lo, hi; UNPK(lo, hi, acc[i][j2]);
            int c0 = bn + tc * 4 + 2 * j2;
            C[(size_t)row * N + c0]     = lo + bias[c0];
            C[(size_t)row * N + c0 + 1] = hi + bias[c0 + 1];
        }
    }
}

// fused output-GEMM slice: warp w does K-slice [w*64,+64) for cols [8bid,+8)
__device__ __forceinline__ void gemm_slice(int s_h, const ulonglong2* __restrict__ swd2,
                                           ull* __restrict__ pg, int w, int lane) {
    const float* hgp = g_hb + ((size_t)s_h * 1024 + w * 64) * 32 + lane;
    ull ga0 = 0, ga1 = 0, ga2 = 0, ga3 = 0;
#pragma unroll 8
    for (int kk = 0; kk < 64; kk++) {
        float hv = __ldcg(hgp + (size_t)kk * 32);
        ull hd; PACKDUP(hd, hv);
        ulonglong2 w01 = swd2[(w * 64 + kk) * 2];
        ulonglong2 w23 = swd2[(w * 64 + kk) * 2 + 1];
        FMA2(ga0, w01.x, hd);
        FMA2(ga1, w01.y, hd);
        FMA2(ga2, w23.x, hd);
        FMA2(ga3, w23.y, hd);
    }
    ull* p = pg + (size_t)(w * 32 + lane) * 4;
    *(ulonglong2*)p       = make_ulonglong2(ga0, ga1);
    *(ulonglong2*)(p + 2) = make_ulonglong2(ga2, ga3);
}

__global__ __launch_bounds__(512, 1)
void gru_persist_kernel(const float* __restrict__ bh, const int* __restrict__ y,
                        const float* __restrict__ bd, float* __restrict__ out) {
    extern __shared__ ull smu[];
    ull*        swh  = smu;
    float*      sex  = (float*)(smu + SWH_ULLS);
    ulonglong2* swd2 = (ulonglong2*)((char*)smu + SWD_OFF_B);
    ull*        pg   = (ull*)((char*)smu + PG_OFF_B);

    const int tid  = threadIdx.x;
    const int lane = tid & 31;
    const int w    = tid >> 5;
    const int bg   = lane >> 2;
    const int rg   = lane & 3;
    const int jbase = blockIdx.x * 8;
    const int jb8   = blockIdx.x * 8;

    // one-time: row-pair-packed Wh
    const float* WhTf = (const float*)g_WhT4;
    for (int idx = tid; idx < 12 * 1024; idx += 512) {
        int a = idx >> 10, k = idx & 1023;
        int ru0 = 2 * a, ru1 = 2 * a + 1;
        int r0 = (ru0 % 3) * 1024 + jbase + ru0 / 3;
        int r1 = (ru1 % 3) * 1024 + jbase + ru1 / 3;
        float w0 = WhTf[(size_t)r0 * 1024 + k];
        float w1 = WhTf[(size_t)r1 * 1024 + k];
        ull pk; PACK2(pk, w0, w1);
        swh[(size_t)k * 16 + (a / 3) * 4 + (a % 3)] = pk;
    }
    // one-time: Wd column slice (4 packed pairs per k)
    {
        const ull* wdp = g_Wdp + (size_t)jb8 / 2;   // pair index = col/2 = 4*bid
        for (int idx = tid; idx < 1024 * 2; idx += 512) {
            int k = idx >> 1, h = idx & 1;
            swd2[idx] = make_ulonglong2(wdp[(size_t)k * 512 + 2 * h],
                                        wdp[(size_t)k * 512 + 2 * h + 1]);
        }
    }

    const bool epi = (tid < 256);
    const int ju = epi ? (jbase + w) : jbase;
    float bz = 0.f, br = 0.f, bq = 0.f, hold = 0.f;
    if (epi) {
        bz = bh[ju]; br = bh[DHID + ju]; bq = bh[2 * DHID + ju];
        hold = ((const float*)g_hb)[(size_t)ju * 32 + lane];
    }
    const int it = tid - 256;
    ull bdp = 0;
    if (it >= 0 && it < 128) {
        int np = it & 3;
        PACK2(bdp, bd[jb8 + 2 * np], bd[jb8 + 2 * np + 1]);
    }
    __syncthreads();

    const int k0w = w * 64;
    const ull* swk = swh + (size_t)k0w * 16 + rg * 4;

    for (int s = 1; s <= TSTEPS; ++s) {
        float ez = 0.f, er = 0.f, eq = 0.f;
        if (epi) {
            int tok = (s == 1) ? 0 : __ldg(&y[lane * 512 + (s - 2)]);
            const float* ep = g_Eproj + (size_t)tok * N3;
            ez = __ldg(ep + ju);
            er = __ldg(ep + DHID + ju);
            eq = __ldg(ep + 2 * DHID + ju);
        }

        ull acc[12];
#pragma unroll
        for (int r = 0; r < 12; r++) acc[r] = 0ull;

        const float* hbase = g_hb + ((size_t)(s - 1) * 1024 + k0w) * 32 + bg * 4;
        uint4 hpre[4];
#pragma unroll
        for (int i = 0; i < 4; i++)
            hpre[i] = __ldcg((const uint4*)(hbase + (size_t)i * 32));

#pragma unroll 8
        for (int kk = 0; kk < 64; kk++) {
            uint4 hc = hpre[kk & 3];
            int pf = (kk + 4 <= 63) ? (kk + 4) : 63;
            hpre[kk & 3] = __ldcg((const uint4*)(hbase + (size_t)pf * 32));

            const ull* wk = swk + (size_t)kk * 16;
            ulonglong2 wv01 = *(const ulonglong2*)wk;
            ull wv2 = wk[2];

            ull hd0, hd1, hd2, hd3;
            PACKDUP(hd0, __uint_as_float(hc.x));
            PACKDUP(hd1, __uint_as_float(hc.y));
            PACKDUP(hd2, __uint_as_float(hc.z));
            PACKDUP(hd3, __uint_as_float(hc.w));

            FMA2(acc[0], wv01.x, hd0); FMA2(acc[1], wv01.x, hd1);
            FMA2(acc[2], wv01.x, hd2); FMA2(acc[3], wv01.x, hd3);
            FMA2(acc[4], wv01.y, hd0); FMA2(acc[5], wv01.y, hd1);
            FMA2(acc[6], wv01.y, hd2); FMA2(acc[7], wv01.y, hd3);
            FMA2(acc[8],  wv2,   hd0); FMA2(acc[9],  wv2,   hd1);
            FMA2(acc[10], wv2,   hd2); FMA2(acc[11], wv2,   hd3);
        }

#pragma unroll
        for (int p = 0; p < 3; p++) {
#pragma unroll
            for (int bb = 0; bb < 4; bb++) {
                float lo, hi; UNPK(lo, hi, acc[p * 4 + bb]);
                int ru = (rg * 3 + p) * 2;
                int b  = bg * 4 + bb;
                sex[(w * 24 + ru)     * 33 + b] = lo;
                sex[(w * 24 + ru + 1) * 33 + b] = hi;
            }
        }

        if (s >= 2) gemm_slice(s - 1, swd2, pg, w, lane);
        __syncthreads();

        if (epi) {
            float hz = bz, hr = br, hqv = bq;
#pragma unroll
            for (int w2 = 0; w2 < 16; w2++) {
                int base = (w2 * 24 + w * 3) * 33 + lane;
                hz  += sex[base];
                hr  += sex[base + 33];
                hqv += sex[base + 66];
            }
            float zg = __fdividef(1.f, 1.f + __expf(-(ez + hz)));
            float rg2 = __fdividef(1.f, 1.f + __expf(-(er + hr)));
            float xq = eq + rg2 * hqv;
            float e2 = __expf(2.f * xq);
            float hc = 1.f - __fdividef(2.f, e2 + 1.f);
            float hn = zg * hold + (1.f - zg) * hc;
            hold = hn;
            __stcg(&g_hb[((size_t)s * 1024 + ju) * 32 + lane], hn);
        } else if (it < 128 && s >= 2) {
            int b = it >> 2, np = it & 3;
            ull sum = bdp;
#pragma unroll
            for (int w2 = 0; w2 < 16; w2++)
                ADD2(sum, pg[(size_t)(w2 * 32 + b) * 4 + np]);
            size_t o = ((size_t)b * 513 + (s - 2)) * 1024 + jb8 + 2 * np;
            __stcg((ull*)&out[o], sum);
        }

        __syncthreads();
        if (tid == 0) {
            asm volatile("red.release.gpu.global.add.u32 [%0], %1;"
                         :: "l"(&g_cnt[s]), "r"(1u) : "memory");
            unsigned v;
            do {
                asm volatile("ld.acquire.gpu.global.u32 %0, [%1];"
                             : "=r"(v) : "l"(&g_cnt[s]) : "memory");
            } while (v < (unsigned)NCTA);
        }
        __syncthreads();
    }

    // tail: output row t = 512 uses h[513]
    gemm_slice(TSTEPS, swd2, pg, w, lane);
    __syncthreads();
    if (it >= 0 && it < 128) {
        int b = it >> 2, np = it & 3;
        ull sum = bdp;
#pragma unroll
        for (int w2 = 0; w2 < 16; w2++)
            ADD2(sum, pg[(size_t)(w2 * 32 + b) * 4 + np]);
        size_t o = ((size_t)b * 513 + 512) * 1024 + jb8 + 2 * np;
        __stcg((ull*)&out[o], sum);
    }
}

extern "C" void kernel_launch(void* const* d_in, const int* in_sizes, int n_in,
                              void* d_out, int out_size) {
    const int*   y   = (const int*)d_in[0];
    const float* emb = (const float*)d_in[1];
    const float* Wx  = (const float*)d_in[2];
    const float* Wh  = (const float*)d_in[3];
    const float* bx  = (const float*)d_in[4];
    const float* bh  = (const float*)d_in[5];
    const float* Wd  = (const float*)d_in[6];
    const float* bd  = (const float*)d_in[7];
    const float* h0  = (const float*)d_in[8];
    float* out = (float*)d_out;

    float *pE;
    cudaGetSymbolAddress((void**)&pE, g_Eproj);

    cudaFuncSetAttribute(gru_persist_kernel,
                         cudaFuncAttributeMaxDynamicSharedMemorySize, STEP_SMEM);

    init_kernel<<<32, 1024>>>(h0);
    transpose_wh_kernel<<<dim3(96, 32), dim3(32, 32)>>>(Wh);
    pack_wd_kernel<<<1024, 512>>>(Wd);
    gemm_bias_kernel<<<dim3(48, 16), 256>>>(emb, Wx, bx, pE, 1024, N3, 1024);
    // persistent GRU recurrence + fused output projection (one launch)
    gru_persist_kernel<<<NCTA, 512, STEP_SMEM>>>(bh, y, bd, out);
}

// round 14
// speedup vs baseline: 1.0473x; 1.0049x over previous
#include <cuda_runtime.h>
#include <math.h>

typedef unsigned long long ull;

#define DHID   1024
#define BATCH  32
#define TSTEPS 513
#define N3     3072
#define NCTA   128

// SMEM layout (bytes): swh 131072 | sex 50688 | sWd 32768 | pg 16384 = 230912
#define SWH_ULLS   (1024 * 16)
#define SEX_FLOATS (16 * 24 * 33)
#define SWD_OFF_B  (SWH_ULLS * 8 + SEX_FLOATS * 4)
#define PG_OFF_B   (SWD_OFF_B + 1024 * 4 * 8)
#define STEP_SMEM  (PG_OFF_B + 16 * 32 * 4 * 8)

#define FMA2(acc, a, b) asm("fma.rn.f32x2 %0, %1, %2, %0;" : "+l"(acc) : "l"(a), "l"(b))
#define ADD2(acc, a)    asm("add.rn.f32x2 %0, %0, %1;" : "+l"(acc) : "l"(a))
#define PACKDUP(d, v)   asm("mov.b64 %0, {%1, %1};" : "=l"(d) : "f"(v))
#define PACK2(d, lo, hi) asm("mov.b64 %0, {%1, %2};" : "=l"(d) : "f"(lo), "f"(hi))
#define UNPK(lo, hi, v) asm("mov.b64 {%0, %1}, %2;" : "=f"(lo), "=f"(hi) : "l"(v))

__device__ float g_Eproj[1024 * N3];
__device__ uint4 g_WhT4[(size_t)N3 * (DHID / 4)];
__device__ float g_hb[(size_t)(TSTEPS + 1) * DHID * BATCH];
__device__ ull   g_Wdp[(size_t)1024 * 512];      // Wd packed col-pairs [k][512]
__device__ unsigned g_cnt[TSTEPS + 2];

__global__ void init_kernel(const float* __restrict__ h0) {
    int idx = blockIdx.x * blockDim.x + threadIdx.x;
    g_hb[idx] = h0[idx >> 5];
    if (idx < TSTEPS + 2) g_cnt[idx] = 0;
}

__global__ void transpose_wh_kernel(const float* __restrict__ Wh) {
    __shared__ float t[32][33];
    int j = blockIdx.x * 32 + threadIdx.x;
    int d = blockIdx.y * 32 + threadIdx.y;
    t[threadIdx.y][threadIdx.x] = Wh[(size_t)d * N3 + j];
    __syncthreads();
    int dd = blockIdx.y * 32 + threadIdx.x;
    int jj = blockIdx.x * 32 + threadIdx.y;
    ((float*)g_WhT4)[(size_t)jj * DHID + dd] = t[threadIdx.x][threadIdx.y];
}

__global__ void pack_wd_kernel(const float* __restrict__ Wd) {
    int idx = blockIdx.x * blockDim.x + threadIdx.x;     // 1024*512
    int k = idx >> 9, p = idx & 511;
    ull v; PACK2(v, Wd[(size_t)k * 1024 + 2 * p], Wd[(size_t)k * 1024 + 2 * p + 1]);
    g_Wdp[idx] = v;
}

// Eproj GEMM: C = A[M,K]*B[K,N] + bias (row-major)
__global__ __launch_bounds__(256)
void gemm_bias_kernel(const float* __restrict__ A, const float* __restrict__ Bm,
                      const float* __restrict__ bias, float* __restrict__ C,
                      int M, int N, int K) {
    __shared__ ull   sAd[32][65];
    __shared__ float sB[32][64];
    int bm = blockIdx.y * 64, bn = blockIdx.x * 64;
    int tid = threadIdx.x;
    int tr = tid >> 4, tc = tid & 15;
    ull acc[4][2];
#pragma unroll
    for (int i = 0; i < 4; i++) { acc[i][0] = 0ull; acc[i][1] = 0ull; }
    for (int k0 = 0; k0 < K; k0 += 32) {
#pragma unroll
        for (int i = tid; i < 64 * 32; i += 256) {
            int r = i >> 5, cc = i & 31;
            int gr = bm + r;
            float v = (gr < M) ? A[(size_t)gr * K + k0 + cc] : 0.f;
            ull dv; PACKDUP(dv, v);
            sAd[cc][r] = dv;
        }
#pragma unroll
        for (int i = tid; i < 32 * 64; i += 256) {
            int r = i >> 6, cc = i & 63;
            sB[r][cc] = Bm[(size_t)(k0 + r) * N + bn + cc];
        }
        __syncthreads();
#pragma unroll
        for (int kk = 0; kk < 32; kk++) {
            ull a0 = sAd[kk][tr * 4 + 0];
            ull a1 = sAd[kk][tr * 4 + 1];
            ull a2 = sAd[kk][tr * 4 + 2];
            ull a3 = sAd[kk][tr * 4 + 3];
            ull b0 = *(const ull*)&sB[kk][tc * 4];
            ull b1 = *(const ull*)&sB[kk][tc * 4 + 2];
            FMA2(acc[0][0], a0, b0); FMA2(acc[0][1], a0, b1);
            FMA2(acc[1][0], a1, b0); FMA2(acc[1][1], a1, b1);
            FMA2(acc[2][0], a2, b0); FMA2(acc[2][1], a2, b1);
            FMA2(acc[3][0], a3, b0); FMA2(acc[3][1], a3, b1);
        }
        __syncthreads();
    }
#pragma unroll
    for (int i = 0; i < 4; i++) {
        int row = bm + tr * 4 + i;
        if (row >= M) continue;
#pragma unroll
        for (int j2 = 0; j2 < 2; j2++) {
            float lo, hi; UNPK(lo, hi, acc[i][j2]);
            int c0 = bn + tc * 4 + 2 * j2;
            C[(size_t)row * N + c0]     = lo + bias[c0];
            C[(size_t)row * N + c0 + 1] = hi + bias[c0 + 1];
        }
    }
}

// fused output-GEMM slice: warp w does K-slice [w*64,+64) for cols [8bid,+8)
__device__ __forceinline__ void gemm_slice(int s_h, const ulonglong2* __restrict__ swd2,
                                           ull* __restrict__ pg, int w, int lane) {
    const float* hgp = g_hb + ((size_t)s_h * 1024 + w * 64) * 32 + lane;
    ull ga0 = 0, ga1 = 0, ga2 = 0, ga3 = 0;
#pragma unroll 8
    for (int kk = 0; kk < 64; kk++) {
        float hv = __ldcg(hgp + (size_t)kk * 32);
        ull hd; PACKDUP(hd, hv);
        ulonglong2 w01 = swd2[(w * 64 + kk) * 2];
        ulonglong2 w23 = swd2[(w * 64 + kk) * 2 + 1];
        FMA2(ga0, w01.x, hd);
        FMA2(ga1, w01.y, hd);
        FMA2(ga2, w23.x, hd);
        FMA2(ga3, w23.y, hd);
    }
    ull* p = pg + (size_t)(w * 32 + lane) * 4;
    *(ulonglong2*)p       = make_ulonglong2(ga0, ga1);
    *(ulonglong2*)(p + 2) = make_ulonglong2(ga2, ga3);
}

__global__ __launch_bounds__(512, 1)
void gru_persist_kernel(const float* __restrict__ bh, const int* __restrict__ y,
                        const float* __restrict__ bd, float* __restrict__ out) {
    extern __shared__ ull smu[];
    ull*        swh  = smu;
    float*      sex  = (float*)(smu + SWH_ULLS);
    ulonglong2* swd2 = (ulonglong2*)((char*)smu + SWD_OFF_B);
    ull*        pg   = (ull*)((char*)smu + PG_OFF_B);

    const int tid  = threadIdx.x;
    const int lane = tid & 31;
    const int w    = tid >> 5;
    const int bg   = lane >> 2;
    const int rg   = lane & 3;
    const int jbase = blockIdx.x * 8;
    const int jb8   = blockIdx.x * 8;

    // one-time: row-pair-packed Wh
    const float* WhTf = (const float*)g_WhT4;
    for (int idx = tid; idx < 12 * 1024; idx += 512) {
        int a = idx >> 10, k = idx & 1023;
        int ru0 = 2 * a, ru1 = 2 * a + 1;
        int r0 = (ru0 % 3) * 1024 + jbase + ru0 / 3;
        int r1 = (ru1 % 3) * 1024 + jbase + ru1 / 3;
        float w0 = WhTf[(size_t)r0 * 1024 + k];
        float w1 = WhTf[(size_t)r1 * 1024 + k];
        ull pk; PACK2(pk, w0, w1);
        swh[(size_t)k * 16 + (a / 3) * 4 + (a % 3)] = pk;
    }
    // one-time: Wd column slice (4 packed pairs per k)
    {
        const ull* wdp = g_Wdp + (size_t)jb8 / 2;   // pair index = col/2 = 4*bid
        for (int idx = tid; idx < 1024 * 2; idx += 512) {
            int k = idx >> 1, h = idx & 1;
            swd2[idx] = make_ulonglong2(wdp[(size_t)k * 512 + 2 * h],
                                        wdp[(size_t)k * 512 + 2 * h + 1]);
        }
    }

    const bool epi = (tid < 256);
    const int ju = epi ? (jbase + w) : jbase;
    float bz = 0.f, br = 0.f, bq = 0.f, hold = 0.f;
    if (epi) {
        bz = bh[ju]; br = bh[DHID + ju]; bq = bh[2 * DHID + ju];
        hold = ((const float*)g_hb)[(size_t)ju * 32 + lane];
    }
    const int it = tid - 256;
    ull bdp = 0;
    if (it >= 0 && it < 128) {
        int np = it & 3;
        PACK2(bdp, bd[jb8 + 2 * np], bd[jb8 + 2 * np + 1]);
    }
    __syncthreads();

    const int k0w = w * 64;
    const ull* swk = swh + (size_t)k0w * 16 + rg * 4;

    for (int s = 1; s <= TSTEPS; ++s) {
        float ez = 0.f, er = 0.f, eq = 0.f;
        if (epi) {
            int tok = (s == 1) ? 0 : __ldg(&y[lane * 512 + (s - 2)]);
            const float* ep = g_Eproj + (size_t)tok * N3;
            ez = __ldg(ep + ju);
            er = __ldg(ep + DHID + ju);
            eq = __ldg(ep + 2 * DHID + ju);
        }

        ull acc[12];
#pragma unroll
        for (int r = 0; r < 12; r++) acc[r] = 0ull;

        const float* hbase = g_hb + ((size_t)(s - 1) * 1024 + k0w) * 32 + bg * 4;
        uint4 hpre[4];
#pragma unroll
        for (int i = 0; i < 4; i++)
            hpre[i] = __ldcg((const uint4*)(hbase + (size_t)i * 32));

#pragma unroll 8
        for (int kk = 0; kk < 64; kk++) {
            uint4 hc = hpre[kk & 3];
            int pf = (kk + 4 <= 63) ? (kk + 4) : 63;
            hpre[kk & 3] = __ldcg((const uint4*)(hbase + (size_t)pf * 32));

            const ull* wk = swk + (size_t)kk * 16;
            ulonglong2 wv01 = *(const ulonglong2*)wk;
            ull wv2 = wk[2];

            ull hd0, hd1, hd2, hd3;
            PACKDUP(hd0, __uint_as_float(hc.x));
            PACKDUP(hd1, __uint_as_float(hc.y));
            PACKDUP(hd2, __uint_as_float(hc.z));
            PACKDUP(hd3, __uint_as_float(hc.w));

            FMA2(acc[0], wv01.x, hd0); FMA2(acc[1], wv01.x, hd1);
            FMA2(acc[2], wv01.x, hd2); FMA2(acc[3], wv01.x, hd3);
            FMA2(acc[4], wv01.y, hd0); FMA2(acc[5], wv01.y, hd1);
            FMA2(acc[6], wv01.y, hd2); FMA2(acc[7], wv01.y, hd3);
            FMA2(acc[8],  wv2,   hd0); FMA2(acc[9],  wv2,   hd1);
            FMA2(acc[10], wv2,   hd2); FMA2(acc[11], wv2,   hd3);
        }

#pragma unroll
        for (int p = 0; p < 3; p++) {
#pragma unroll
            for (int bb = 0; bb < 4; bb++) {
                float lo, hi; UNPK(lo, hi, acc[p * 4 + bb]);
                int ru = (rg * 3 + p) * 2;
                int b  = bg * 4 + bb;
                sex[(w * 24 + ru)     * 33 + b] = lo;
                sex[(w * 24 + ru + 1) * 33 + b] = hi;
            }
        }

        if (s >= 2) gemm_slice(s - 1, swd2, pg, w, lane);
        __syncthreads();

        if (epi) {
            float hz = bz, hr = br, hqv = bq;
#pragma unroll
            for (int w2 = 0; w2 < 16; w2++) {
                int base = (w2 * 24 + w * 3) * 33 + lane;
                hz  += sex[base];
                hr  += sex[base + 33];
                hqv += sex[base + 66];
            }
            float zg = __fdividef(1.f, 1.f + __expf(-(ez + hz)));
            float rg2 = __fdividef(1.f, 1.f + __expf(-(er + hr)));
            float xq = eq + rg2 * hqv;
            float e2 = __expf(2.f * xq);
            float hc = 1.f - __fdividef(2.f, e2 + 1.f);
            float hn = zg * hold + (1.f - zg) * hc;
            hold = hn;
            __stcg(&g_hb[((size_t)s * 1024 + ju) * 32 + lane], hn);
        } else if (it < 128 && s >= 2) {
            int b = it >> 2, np = it & 3;
            ull sum = bdp;
#pragma unroll
            for (int w2 = 0; w2 < 16; w2++)
                ADD2(sum, pg[(size_t)(w2 * 32 + b) * 4 + np]);
            size_t o = ((size_t)b * 513 + (s - 2)) * 1024 + jb8 + 2 * np;
            __stcg((ull*)&out[o], sum);
        }

        __syncthreads();
        if (tid == 0) {
            asm volatile("red.release.gpu.global.add.u32 [%0], %1;"
                         :: "l"(&g_cnt[s]), "r"(1u) : "memory");
            unsigned v;
            do {
                asm volatile("ld.acquire.gpu.global.u32 %0, [%1];"
                             : "=r"(v) : "l"(&g_cnt[s]) : "memory");
            } while (v < (unsigned)NCTA);
        }
        __syncthreads();
    }

    // tail: output row t = 512 uses h[513]
    gemm_slice(TSTEPS, swd2, pg, w, lane);
    __syncthreads();
    if (it >= 0 && it < 128) {
        int b = it >> 2, np = it & 3;
        ull sum = bdp;
#pragma unroll
        for (int w2 = 0; w2 < 16; w2++)
            ADD2(sum, pg[(size_t)(w2 * 32 + b) * 4 + np]);
        size_t o = ((size_t)b * 513 + 512) * 1024 + jb8 + 2 * np;
        __stcg((ull*)&out[o], sum);
    }
}

extern "C" void kernel_launch(void* const* d_in, const int* in_sizes, int n_in,
                              void* d_out, int out_size) {
    const int*   y   = (const int*)d_in[0];
    const float* emb = (const float*)d_in[1];
    const float* Wx  = (const float*)d_in[2];
    const float* Wh  = (const float*)d_in[3];
    const float* bx  = (const float*)d_in[4];
    const float* bh  = (const float*)d_in[5];
    const float* Wd  = (const float*)d_in[6];
    const float* bd  = (const float*)d_in[7];
    const float* h0  = (const float*)d_in[8];
    float* out = (float*)d_out;

    float *pE;
    cudaGetSymbolAddress((void**)&pE, g_Eproj);

    cudaFuncSetAttribute(gru_persist_kernel,
                         cudaFuncAttributeMaxDynamicSharedMemorySize, STEP_SMEM);

    init_kernel<<<32, 1024>>>(h0);
    transpose_wh_kernel<<<dim3(96, 32), dim3(32, 32)>>>(Wh);
    pack_wd_kernel<<<1024, 512>>>(Wd);
    gemm_bias_kernel<<<dim3(48, 16), 256>>>(emb, Wx, bx, pE, 1024, N3, 1024);
    // persistent GRU recurrence + fused output projection (one launch)
    gru_persist_kernel<<<NCTA, 512, STEP_SMEM>>>(bh, y, bd, out);
}